// round 9
// baseline (speedup 1.0000x reference)
#include <cuda_runtime.h>
#include <cuda_fp16.h>
#include <cstdint>

#define NU 100000
#define NP 200000
#define H  128
#define EV 500000
#define EL 150000
#define NALL (2*NP + 2*NU)        // 600000
#define GP 1563                   // ceil(NP/128)
#define GU 782                    // ceil(NU/128)

// ---------------- scratch layout (4-byte float units) ----------------
#define OFF_XU0 0LL               // emb_u fp16 (6.4M floats)
#define OFF_XP0 6400000LL         // emb_p fp16 (12.8M)
#define OFF_XU1 19200000LL        // layer-0 user out fp16
#define OFF_XP1 25600000LL        // layer-0 post out fp16
#define OFF_INT 38400000LL
#define OFF_BH  41600000LL        // 4*49152 fp16
#define OFF_BIAS 41698304LL
#define SCRATCH_FLOATS 41700000LL

// int offsets inside int region
#define I_CNT  0
#define I_TOT  600000
#define I_OFFS 600064
#define I_CUR  1200128
#define I_POOL 1800192            // 1.3M entries

__device__ __align__(1024) float g_scratch[SCRATCH_FLOATS];

// ---------------- PTX helpers (base-target safe, sm_80-class) ----------------
__device__ __forceinline__ uint32_t smem_u32(const void* p) {
    uint32_t a;
    asm("{ .reg .u64 t; cvta.to.shared.u64 t, %1; cvt.u32.u64 %0, t; }" : "=r"(a) : "l"(p));
    return a;
}
__device__ __forceinline__ void ldsm_x4(uint32_t& r0, uint32_t& r1, uint32_t& r2, uint32_t& r3,
                                        uint32_t addr) {
    asm volatile("ldmatrix.sync.aligned.m8n8.x4.shared.b16 {%0,%1,%2,%3}, [%4];"
                 : "=r"(r0), "=r"(r1), "=r"(r2), "=r"(r3) : "r"(addr));
}
__device__ __forceinline__ void mma_f16(float* d, const uint32_t* a, const uint32_t* b) {
    asm volatile("mma.sync.aligned.m16n8k16.row.col.f32.f16.f16.f32 "
                 "{%0,%1,%2,%3}, {%4,%5,%6,%7}, {%8,%9}, {%0,%1,%2,%3};"
                 : "+f"(d[0]), "+f"(d[1]), "+f"(d[2]), "+f"(d[3])
                 : "r"(a[0]), "r"(a[1]), "r"(a[2]), "r"(a[3]), "r"(b[0]), "r"(b[1]));
}
__device__ __forceinline__ void cp16(uint32_t dst, const void* src) {
    asm volatile("cp.async.cg.shared.global [%0], [%1], 16;"
                 :: "r"(dst), "l"(src) : "memory");
}
#define CP_COMMIT() asm volatile("cp.async.commit_group;" ::: "memory")
#define CP_WAIT1()  asm volatile("cp.async.wait_group 1;" ::: "memory")
#define CP_WAIT0()  asm volatile("cp.async.wait_group 0;" ::: "memory")

// ---------------- fused prep: zero cnt, B fp16 + bias, emb fp32->fp16 ----------------
#define CVT_GROUPS ((NU + NP) * 16)            // uint4 groups (8 halves)
#define CVT_BLOCKS ((CVT_GROUPS + 255) / 256)  // 18750
#define ZERO_INTS  (NALL + 64)
#define ZERO_BLOCKS ((ZERO_INTS + 1023) / 1024)
#define PREP_GRID (768 + CVT_BLOCKS + ZERO_BLOCKS)
__global__ void k_prep(const float* __restrict__ Wl, const float* __restrict__ bl,
                       const float* __restrict__ Wr,
                       const float* __restrict__ eu, const float* __restrict__ ep,
                       __half* __restrict__ Bh, float* __restrict__ Bias,
                       __half* __restrict__ xu16, __half* __restrict__ xp16,
                       int* __restrict__ cnt) {
    int b = blockIdx.x;
    if (b < 768) {
        int t = b / 192;
        int idx = (b % 192) * 256 + threadIdx.x;   // < 49152
        int layer = t >> 1, isU = t & 1;
        int rV = isU ? 1 : 0, rL = rV + 2;
        int n = idx / 384, k = idx % 384;
        const float* WlV = Wl + (size_t)((layer * 4 + rV) * 128) * 128;
        const float* WlL = Wl + (size_t)((layer * 4 + rL) * 128) * 128;
        const float* WrV = Wr + (size_t)((layer * 4 + rV) * 128) * 128;
        const float* WrL = Wr + (size_t)((layer * 4 + rL) * 128) * 128;
        float v;
        if (k < 128)      v = WlV[n * 128 + k];
        else if (k < 256) v = WlL[n * 128 + (k - 128)];
        else              v = WrV[n * 128 + (k - 256)] + WrL[n * 128 + (k - 256)];
        Bh[(size_t)t * 49152 + idx] = __float2half_rn(v);
        if (idx < 128)
            Bias[t * 128 + idx] = bl[(layer * 4 + rV) * 128 + idx] + bl[(layer * 4 + rL) * 128 + idx];
    } else if (b < 768 + CVT_BLOCKS) {
        long i = (long)(b - 768) * 256 + threadIdx.x;
        if (i >= CVT_GROUPS) return;
        const float* src; __half* dst; long j;
        if (i < (long)NU * 16) { src = eu; dst = xu16; j = i; }
        else                   { src = ep; dst = xp16; j = i - (long)NU * 16; }
        float4 a = __ldg(reinterpret_cast<const float4*>(src) + j * 2);
        float4 c = __ldg(reinterpret_cast<const float4*>(src) + j * 2 + 1);
        __half2 h0 = __floats2half2_rn(a.x, a.y);
        __half2 h1 = __floats2half2_rn(a.z, a.w);
        __half2 h2 = __floats2half2_rn(c.x, c.y);
        __half2 h3 = __floats2half2_rn(c.z, c.w);
        uint4 o;
        o.x = *reinterpret_cast<uint32_t*>(&h0);
        o.y = *reinterpret_cast<uint32_t*>(&h1);
        o.z = *reinterpret_cast<uint32_t*>(&h2);
        o.w = *reinterpret_cast<uint32_t*>(&h3);
        reinterpret_cast<uint4*>(dst)[j] = o;
    } else {
        long i = (long)(b - 768 - CVT_BLOCKS) * 1024 + threadIdx.x * 4;
        if (i + 3 < ZERO_INTS)
            *reinterpret_cast<int4*>(cnt + i) = make_int4(0, 0, 0, 0);
        else
            for (long q = i; q < ZERO_INTS; ++q) cnt[q] = 0;
    }
}

// ---------------- CSR build ----------------
__global__ void k_hist(const int* __restrict__ vs, const int* __restrict__ vd,
                       const int* __restrict__ ls, const int* __restrict__ ld,
                       int* __restrict__ cnt) {
    int i = blockIdx.x * blockDim.x + threadIdx.x;
    if (i < EV) { atomicAdd(&cnt[vd[i]], 1); atomicAdd(&cnt[2*NP + vs[i]], 1); }
    if (i < EL) { atomicAdd(&cnt[NP + ld[i]], 1); atomicAdd(&cnt[2*NP + NU + ls[i]], 1); }
}

__global__ void k_alloc(const int* __restrict__ cnt, int* __restrict__ offs,
                        int* __restrict__ cur, int* __restrict__ tot) {
    int w = blockIdx.x * blockDim.x + threadIdx.x;
    if (w >= NALL) return;
    int c = cnt[w];
    int base = c ? atomicAdd(tot, c) : 0;
    offs[w] = base;
    cur[w] = base;
}

__global__ void k_scatter(const int* __restrict__ vs, const int* __restrict__ vd,
                          const int* __restrict__ ls, const int* __restrict__ ld,
                          int* __restrict__ cur, int* __restrict__ pool) {
    int i = blockIdx.x * blockDim.x + threadIdx.x;
    if (i < EV) {
        int p = atomicAdd(&cur[vd[i]], 1);             pool[p] = vs[i];
        int q = atomicAdd(&cur[2*NP + vs[i]], 1);      pool[q] = vd[i];
    }
    if (i < EL) {
        int p = atomicAdd(&cur[NP + ld[i]], 1);        pool[p] = ls[i];
        int q = atomicAdd(&cur[2*NP + NU + ls[i]], 1); pool[q] = ld[i];
    }
}

// ---------------- fused gather-mean + GEMM ----------------
// out[M,128] = [meanV | meanL | x](M x 384 fp16) @ B^T + bias; fp32 accum.
// blocks [0,GP): posts (gather users); [GP,GP+GU): users (gather posts).
#define RSTRA 136                       // sMean row stride (halves)
#define RSTRB 72                        // B tile row stride (halves)
#define SMEAN_B (128 * RSTRA * 2)       // 34816 bytes
#define BCHUNK_B (128 * RSTRB * 2)      // 18432 bytes
#define GSMEM (SMEAN_B + 2 * BCHUNK_B)  // 71680 bytes

template <bool OUTH>   // true: fp16 out + relu (layer 0); false: fp32 out (layer 1)
__global__ void __launch_bounds__(256, 2)
gemm_fused(const int* __restrict__ offs, const int* __restrict__ cnt,
           const int* __restrict__ pool,
           const __half* __restrict__ xu, const __half* __restrict__ xp,
           const __half* __restrict__ BhP, const __half* __restrict__ BhU,
           const float* __restrict__ biasP, const float* __restrict__ biasU,
           void* __restrict__ outPv, void* __restrict__ outUv) {
    extern __shared__ __align__(16) __half sm[];
    __half* sMean = sm;
    const uint32_t uA = smem_u32(sMean);
    const uint32_t uBb[2] = {uA + SMEAN_B, uA + SMEAN_B + BCHUNK_B};

    const bool isP = blockIdx.x < GP;
    const int row0 = (isP ? blockIdx.x : blockIdx.x - GP) << 7;
    const int M = isP ? NP : NU;
    const int slotV = isP ? 0 : 2 * NP;
    const int slotL = isP ? NP : 2 * NP + NU;
    const __half* Xopp  = isP ? xu : xp;   // gather source
    const __half* Xself = isP ? xp : xu;
    const __half* Bh = isP ? BhP : BhU;
    const float* bias = isP ? biasP : biasU;
    void* outv = isP ? outPv : outUv;

    const int tid = threadIdx.x;
    const int warp = tid >> 5, lane = tid & 31;
    const int wm = warp & 3, wn = warp >> 2;

    float acc[2][8][4];
#pragma unroll
    for (int i = 0; i < 2; ++i)
#pragma unroll
        for (int j = 0; j < 8; ++j)
#pragma unroll
            for (int q = 0; q < 4; ++q) acc[i][j][q] = 0.f;

    // B staging indices (per thread: 32 halves of one row)
    const int sr = tid >> 1;
    const int shf = (tid & 1) << 5;
    const uint32_t soffB = (uint32_t)(sr * RSTRB + shf) * 2;

    // gather indices: 8 threads per row, 16 cols each
    const int gq = tid & 7;              // column group (16 halves)
    const int gr0 = tid >> 3;            // row base (0..31), +32 per pass

    const int lA_row = lane & 15, lA_k = (lane >> 4) << 3;
    const int lB_row = ((lane >> 4) & 1) * 8 + (lane & 7);
    const int lB_k = ((lane >> 3) & 1) << 3;

    auto stageB = [&](int c) {
        const __half* bp = Bh + (size_t)sr * 384 + c * 64 + shf;
        const uint32_t dst = uBb[c & 1] + soffB;
#pragma unroll
        for (int q = 0; q < 4; ++q)
            cp16(dst + q * 16, bp + q * 8);
    };

    stageB(0);
    CP_COMMIT();

#pragma unroll 1
    for (int p = 0; p < 3; ++p) {
        // ---- phase p: fill sMean (gather-mean for p<2, self copy for p==2) ----
#pragma unroll 1
        for (int pass = 0; pass < 4; ++pass) {
            const int r = gr0 + pass * 32;
            const int node = row0 + r;
            uint4 o0 = make_uint4(0, 0, 0, 0), o1 = make_uint4(0, 0, 0, 0);
            if (node < M) {
                if (p == 2) {
                    const uint4* sp = reinterpret_cast<const uint4*>(
                        Xself + (size_t)node * H + gq * 16);
                    o0 = __ldg(sp);
                    o1 = __ldg(sp + 1);
                } else {
                    const int slot = (p == 0 ? slotV : slotL) + node;
                    const int beg = __ldg(offs + slot);
                    const int deg = __ldg(cnt + slot);
                    float2 sa[8];
#pragma unroll
                    for (int j = 0; j < 8; ++j) sa[j] = make_float2(0.f, 0.f);
                    for (int e = 0; e < deg; ++e) {
                        const int nb = __ldg(pool + beg + e);
                        const uint4* sp = reinterpret_cast<const uint4*>(
                            Xopp + (size_t)nb * H + gq * 16);
                        uint4 v0 = __ldg(sp);
                        uint4 v1 = __ldg(sp + 1);
                        float2 f;
                        f = __half22float2(*reinterpret_cast<__half2*>(&v0.x)); sa[0].x += f.x; sa[0].y += f.y;
                        f = __half22float2(*reinterpret_cast<__half2*>(&v0.y)); sa[1].x += f.x; sa[1].y += f.y;
                        f = __half22float2(*reinterpret_cast<__half2*>(&v0.z)); sa[2].x += f.x; sa[2].y += f.y;
                        f = __half22float2(*reinterpret_cast<__half2*>(&v0.w)); sa[3].x += f.x; sa[3].y += f.y;
                        f = __half22float2(*reinterpret_cast<__half2*>(&v1.x)); sa[4].x += f.x; sa[4].y += f.y;
                        f = __half22float2(*reinterpret_cast<__half2*>(&v1.y)); sa[5].x += f.x; sa[5].y += f.y;
                        f = __half22float2(*reinterpret_cast<__half2*>(&v1.z)); sa[6].x += f.x; sa[6].y += f.y;
                        f = __half22float2(*reinterpret_cast<__half2*>(&v1.w)); sa[7].x += f.x; sa[7].y += f.y;
                    }
                    const float inv = 1.0f / fmaxf((float)deg, 1.0f);
                    __half2 h;
                    h = __floats2half2_rn(sa[0].x * inv, sa[0].y * inv); o0.x = *reinterpret_cast<uint32_t*>(&h);
                    h = __floats2half2_rn(sa[1].x * inv, sa[1].y * inv); o0.y = *reinterpret_cast<uint32_t*>(&h);
                    h = __floats2half2_rn(sa[2].x * inv, sa[2].y * inv); o0.z = *reinterpret_cast<uint32_t*>(&h);
                    h = __floats2half2_rn(sa[3].x * inv, sa[3].y * inv); o0.w = *reinterpret_cast<uint32_t*>(&h);
                    h = __floats2half2_rn(sa[4].x * inv, sa[4].y * inv); o1.x = *reinterpret_cast<uint32_t*>(&h);
                    h = __floats2half2_rn(sa[5].x * inv, sa[5].y * inv); o1.y = *reinterpret_cast<uint32_t*>(&h);
                    h = __floats2half2_rn(sa[6].x * inv, sa[6].y * inv); o1.z = *reinterpret_cast<uint32_t*>(&h);
                    h = __floats2half2_rn(sa[7].x * inv, sa[7].y * inv); o1.w = *reinterpret_cast<uint32_t*>(&h);
                }
            }
            uint4* dp = reinterpret_cast<uint4*>(sMean + r * RSTRA + gq * 16);
            dp[0] = o0;
            dp[1] = o1;
        }

        // ---- 2 K-chunks of MMAs on this phase's sMean ----
#pragma unroll
        for (int s = 0; s < 2; ++s) {
            const int c = 2 * p + s;
            if (c < 5) {
                stageB(c + 1);
                CP_COMMIT();
                CP_WAIT1();
            } else {
                CP_WAIT0();
            }
            __syncthreads();   // sMean written + B buffer ready

            const uint32_t uB = uBb[c & 1];
#pragma unroll
            for (int ks = 0; ks < 4; ++ks) {
                uint32_t af[2][4];
#pragma unroll
                for (int mt = 0; mt < 2; ++mt) {
                    uint32_t eo = ((wm * 32 + mt * 16 + lA_row) * RSTRA + s * 64 + ks * 16 + lA_k) * 2;
                    ldsm_x4(af[mt][0], af[mt][1], af[mt][2], af[mt][3], uA + eo);
                }
                uint32_t bf[4][4];
#pragma unroll
                for (int np = 0; np < 4; ++np) {
                    uint32_t eo = ((wn * 64 + np * 16 + lB_row) * RSTRB + ks * 16 + lB_k) * 2;
                    ldsm_x4(bf[np][0], bf[np][1], bf[np][2], bf[np][3], uB + eo);
                }
#pragma unroll
                for (int mt = 0; mt < 2; ++mt)
#pragma unroll
                    for (int nt = 0; nt < 8; ++nt)
                        mma_f16(acc[mt][nt], af[mt], &bf[nt >> 1][(nt & 1) << 1]);
            }
            __syncthreads();   // done reading before sMean/B overwrite
        }
    }

    // ---- epilogue ----
    const int lr = lane >> 2;
    const int lc = (lane & 3) << 1;
#pragma unroll
    for (int mt = 0; mt < 2; ++mt) {
        int r0 = row0 + wm * 32 + mt * 16 + lr;
#pragma unroll
        for (int nt = 0; nt < 8; ++nt) {
            int cn = wn * 64 + nt * 8 + lc;
            float b0 = __ldg(bias + cn), b1 = __ldg(bias + cn + 1);
            float* a4 = acc[mt][nt];
            if (OUTH) {
                __half* o16 = (__half*)outv;
                if (r0 < M) {
                    __half2 h = __floats2half2_rn(fmaxf(a4[0] + b0, 0.f), fmaxf(a4[1] + b1, 0.f));
                    *reinterpret_cast<__half2*>(o16 + (size_t)r0 * H + cn) = h;
                }
                if (r0 + 8 < M) {
                    __half2 h = __floats2half2_rn(fmaxf(a4[2] + b0, 0.f), fmaxf(a4[3] + b1, 0.f));
                    *reinterpret_cast<__half2*>(o16 + (size_t)(r0 + 8) * H + cn) = h;
                }
            } else {
                float* o32 = (float*)outv;
                if (r0 < M)
                    *reinterpret_cast<float2*>(o32 + (size_t)r0 * H + cn) =
                        make_float2(a4[0] + b0, a4[1] + b1);
                if (r0 + 8 < M)
                    *reinterpret_cast<float2*>(o32 + (size_t)(r0 + 8) * H + cn) =
                        make_float2(a4[2] + b0, a4[3] + b1);
            }
        }
    }
}

// ---------------- host ----------------
extern "C" void kernel_launch(void* const* d_in, const int* in_sizes, int n_in,
                              void* d_out, int out_size) {
    (void)in_sizes; (void)n_in; (void)out_size;
    const float* emb_u = (const float*)d_in[0];
    const float* emb_p = (const float*)d_in[1];
    const float* W_l   = (const float*)d_in[2];
    const float* b_l   = (const float*)d_in[3];
    const float* W_r   = (const float*)d_in[4];
    const int*   ev_s  = (const int*)d_in[5];
    const int*   ev_d  = (const int*)d_in[6];
    const int*   el_s  = (const int*)d_in[7];
    const int*   el_d  = (const int*)d_in[8];

    float* base = 0;
    cudaGetSymbolAddress((void**)&base, g_scratch);

    __half* xu0  = (__half*)(base + OFF_XU0);
    __half* xp0  = (__half*)(base + OFF_XP0);
    __half* xu1  = (__half*)(base + OFF_XU1);
    __half* xp1  = (__half*)(base + OFF_XP1);
    int*   ip  = (int*)(base + OFF_INT);
    int* cnt  = ip + I_CNT;
    int* tot  = ip + I_TOT;
    int* offs = ip + I_OFFS;
    int* cur  = ip + I_CUR;
    int* pool = ip + I_POOL;
    __half* Bh = (__half*)(base + OFF_BH);
    float* Bias = base + OFF_BIAS;

    float* outU = (float*)d_out;
    float* outP = outU + (size_t)NU * H;

    cudaFuncSetAttribute(gemm_fused<true>,  cudaFuncAttributeMaxDynamicSharedMemorySize, GSMEM);
    cudaFuncSetAttribute(gemm_fused<false>, cudaFuncAttributeMaxDynamicSharedMemorySize, GSMEM);

    k_prep<<<PREP_GRID, 256>>>(W_l, b_l, W_r, emb_u, emb_p, Bh, Bias, xu0, xp0, cnt);
    k_hist<<<(EV + 255) / 256, 256>>>(ev_s, ev_d, el_s, el_d, cnt);
    k_alloc<<<(NALL + 255) / 256, 256>>>(cnt, offs, cur, tot);
    k_scatter<<<(EV + 255) / 256, 256>>>(ev_s, ev_d, el_s, el_d, cur, pool);

    // layer 0: fused gather-mean + GEMM (fp16 out + relu)
    gemm_fused<true><<<GP + GU, 256, GSMEM>>>(offs, cnt, pool, xu0, xp0,
                                              Bh + 0 * 49152, Bh + 1 * 49152,
                                              Bias + 0 * 128, Bias + 1 * 128,
                                              xp1, xu1);
    // layer 1: fused gather-mean + GEMM (fp32 out)
    gemm_fused<false><<<GP + GU, 256, GSMEM>>>(offs, cnt, pool, xu1, xp1,
                                               Bh + 2 * 49152, Bh + 3 * 49152,
                                               Bias + 2 * 128, Bias + 3 * 128,
                                               outP, outU);
}